// round 1
// baseline (speedup 1.0000x reference)
#include <cuda_runtime.h>
#include <math.h>
#include <float.h>

#define NN 50000
#define EE 300000
#define EL (EE + NN)          // edges + self loops
#define GG 64
#define FD 64
#define NH 4
#define HC 256
#define LATD 256
#define GFD 832               // 64 + 3*256
#define SCAN_B 1024
#define NB1 ((NN + SCAN_B - 1) / SCAN_B)   // 49

// ---------------- device scratch (static, no allocs) ----------------
__device__ float d_n0[NN * FD];
__device__ float d_h [NN * HC];
__device__ float d_x1[NN * HC];
__device__ float d_x2[NN * HC];
__device__ float d_x3[NN * HC];
__device__ float d_as[NN * NH];
__device__ float d_ad[NN * NH];
__device__ int   d_deg[NN];
__device__ int   d_off[NN + 1];
__device__ int   d_cur[NN];
__device__ int   d_csr_src[EL];
__device__ int   d_bsum[NB1 + 1];
__device__ int   d_gstart[GG];
__device__ int   d_gend[GG];
__device__ float d_gfeat[GG * GFD];
__device__ float d_lat[GG * LATD];

// ---------------- CSR build ----------------
__global__ void k_init() {
    int i = blockIdx.x * blockDim.x + threadIdx.x;
    if (i < NN) d_deg[i] = 0;
    if (i < GG) { d_gstart[i] = NN; d_gend[i] = 0; }
    if (i == 0) d_off[0] = 0;
}

__global__ void k_deg(const int* __restrict__ ei) {
    int i = blockIdx.x * blockDim.x + threadIdx.x;
    if (i >= EL) return;
    int dst = (i < EE) ? ei[EE + i] : (i - EE);
    atomicAdd(&d_deg[dst], 1);
}

__global__ void k_scan1() {
    __shared__ int sm[SCAN_B];
    int tid = threadIdx.x;
    int i = blockIdx.x * SCAN_B + tid;
    int v = (i < NN) ? d_deg[i] : 0;
    sm[tid] = v;
    __syncthreads();
    for (int d = 1; d < SCAN_B; d <<= 1) {
        int t = 0;
        if (tid >= d) t = sm[tid - d];
        __syncthreads();
        sm[tid] += t;
        __syncthreads();
    }
    if (i < NN) d_off[i + 1] = sm[tid];
    if (tid == SCAN_B - 1) d_bsum[blockIdx.x] = sm[tid];
}

__global__ void k_scan2() {
    if (threadIdx.x == 0) {
        int run = 0;
        for (int b = 0; b < NB1; b++) { int v = d_bsum[b]; d_bsum[b] = run; run += v; }
    }
}

__global__ void k_scan3() {
    int i = blockIdx.x * blockDim.x + threadIdx.x;
    if (i < NN) d_off[i + 1] += d_bsum[i >> 10];
}

__global__ void k_cursor() {
    int i = blockIdx.x * blockDim.x + threadIdx.x;
    if (i < NN) d_cur[i] = d_off[i];
}

__global__ void k_scatter(const int* __restrict__ ei) {
    int i = blockIdx.x * blockDim.x + threadIdx.x;
    if (i >= EL) return;
    int src, dst;
    if (i < EE) { src = ei[i]; dst = ei[EE + i]; }
    else        { src = i - EE; dst = i - EE; }
    int pos = atomicAdd(&d_cur[dst], 1);
    d_csr_src[pos] = src;
}

__global__ void k_bounds(const int* __restrict__ batch) {
    int i = blockIdx.x * blockDim.x + threadIdx.x;
    if (i >= NN) return;
    int b = batch[i];
    atomicMin(&d_gstart[b], i);
    atomicMax(&d_gend[b], i + 1);
}

// ---------------- input projection: n0 = relu(bf @ bf_W + bf_b) ----------------
__global__ void k_proj(const float* __restrict__ bf, const float* __restrict__ W,
                       const float* __restrict__ b) {
    int t = blockIdx.x * blockDim.x + threadIdx.x;
    if (t >= NN * FD) return;
    int n = t >> 6, f = t & 63;
    const float* r = &bf[n * 5];
    float acc = b[f];
    acc += r[0] * W[0 * FD + f];
    acc += r[1] * W[1 * FD + f];
    acc += r[2] * W[2 * FD + f];
    acc += r[3] * W[3 * FD + f];
    acc += r[4] * W[4 * FD + f];
    d_n0[t] = acc > 0.f ? acc : 0.f;
}

// ---------------- SGEMM: out[NN,256] = x[NN,K] @ W[K,256] (no bias) ----------------
__global__ void __launch_bounds__(256) k_gemm(const float* __restrict__ x,
                                              const float* __restrict__ W,
                                              float* __restrict__ out, int K) {
    __shared__ float As[16][68];
    __shared__ float Bs[16][64];
    int tid = threadIdx.x;
    int bm = blockIdx.x, bn = blockIdx.y;
    int tn = tid & 15, tm = tid >> 4;
    int row0 = bm * 64;
    int am = tid >> 2;          // 0..63
    int ak = (tid & 3) * 4;     // 0,4,8,12
    int bk = tid >> 4;          // 0..15
    int bn4 = (tid & 15) * 4;   // 0..60
    float acc[4][4];
#pragma unroll
    for (int i = 0; i < 4; i++)
#pragma unroll
        for (int j = 0; j < 4; j++) acc[i][j] = 0.f;

    for (int k0 = 0; k0 < K; k0 += 16) {
        float4 av = make_float4(0.f, 0.f, 0.f, 0.f);
        int arow = row0 + am;
        if (arow < NN) av = *(const float4*)&x[arow * K + k0 + ak];
        As[ak + 0][am] = av.x; As[ak + 1][am] = av.y;
        As[ak + 2][am] = av.z; As[ak + 3][am] = av.w;
        float4 bv = *(const float4*)&W[(k0 + bk) * HC + bn * 64 + bn4];
        *(float4*)&Bs[bk][bn4] = bv;
        __syncthreads();
#pragma unroll
        for (int k = 0; k < 16; k++) {
            float4 a4 = *(const float4*)&As[k][tm * 4];
            float4 b4 = *(const float4*)&Bs[k][tn * 4];
            float a[4] = {a4.x, a4.y, a4.z, a4.w};
            float b[4] = {b4.x, b4.y, b4.z, b4.w};
#pragma unroll
            for (int i = 0; i < 4; i++)
#pragma unroll
                for (int j = 0; j < 4; j++) acc[i][j] += a[i] * b[j];
        }
        __syncthreads();
    }
#pragma unroll
    for (int i = 0; i < 4; i++) {
        int r = row0 + tm * 4 + i;
        if (r < NN) {
            float4 o = make_float4(acc[i][0], acc[i][1], acc[i][2], acc[i][3]);
            *(float4*)&out[r * HC + bn * 64 + tn * 4] = o;
        }
    }
}

// ---------------- attention dots: a_s/a_d [NN,4] from h [NN,256] ----------------
__global__ void k_att(const float* __restrict__ h, const float* __restrict__ asw,
                      const float* __restrict__ adw) {
    int w = (blockIdx.x * blockDim.x + threadIdx.x) >> 5;
    int lane = threadIdx.x & 31;
    if (w >= NN) return;
    float pa[4] = {0, 0, 0, 0}, pd[4] = {0, 0, 0, 0};
#pragma unroll
    for (int i = 0; i < 8; i++) {
        int col = lane + 32 * i;
        float hv = h[w * HC + col];
        pa[i >> 1] += hv * __ldg(&asw[col]);
        pd[i >> 1] += hv * __ldg(&adw[col]);
    }
#pragma unroll
    for (int hh = 0; hh < 4; hh++) {
        float a = pa[hh], d = pd[hh];
#pragma unroll
        for (int o = 16; o > 0; o >>= 1) {
            a += __shfl_xor_sync(0xffffffffu, a, o);
            d += __shfl_xor_sync(0xffffffffu, d, o);
        }
        if (lane == 0) { d_as[w * 4 + hh] = a; d_ad[w * 4 + hh] = d; }
    }
}

__device__ __forceinline__ float lrelu(float v) { return v > 0.f ? v : 0.2f * v; }

// ---------------- GAT aggregate: warp per node, softmax over incoming edges ----------------
__global__ void k_agg(const float* __restrict__ h, const float* __restrict__ bias,
                      float* __restrict__ out) {
    int n = (blockIdx.x * blockDim.x + threadIdx.x) >> 5;
    int lane = threadIdx.x & 31;
    if (n >= NN) return;
    int beg = d_off[n], end = d_off[n + 1];
    float4 ad4 = *(const float4*)&d_ad[n * 4];
    float adv[4] = {ad4.x, ad4.y, ad4.z, ad4.w};

    // phase 1: per-head max over edges
    float mx[4] = {-FLT_MAX, -FLT_MAX, -FLT_MAX, -FLT_MAX};
    for (int j = beg + lane; j < end; j += 32) {
        int s = d_csr_src[j];
        float4 a4 = *(const float4*)&d_as[s * 4];
        mx[0] = fmaxf(mx[0], lrelu(a4.x + adv[0]));
        mx[1] = fmaxf(mx[1], lrelu(a4.y + adv[1]));
        mx[2] = fmaxf(mx[2], lrelu(a4.z + adv[2]));
        mx[3] = fmaxf(mx[3], lrelu(a4.w + adv[3]));
    }
#pragma unroll
    for (int hh = 0; hh < 4; hh++)
#pragma unroll
        for (int o = 16; o > 0; o >>= 1)
            mx[hh] = fmaxf(mx[hh], __shfl_xor_sync(0xffffffffu, mx[hh], o));

    // phase 2: per-head sum of exp
    float sm[4] = {0, 0, 0, 0};
    for (int j = beg + lane; j < end; j += 32) {
        int s = d_csr_src[j];
        float4 a4 = *(const float4*)&d_as[s * 4];
        sm[0] += expf(lrelu(a4.x + adv[0]) - mx[0]);
        sm[1] += expf(lrelu(a4.y + adv[1]) - mx[1]);
        sm[2] += expf(lrelu(a4.z + adv[2]) - mx[2]);
        sm[3] += expf(lrelu(a4.w + adv[3]) - mx[3]);
    }
#pragma unroll
    for (int hh = 0; hh < 4; hh++)
#pragma unroll
        for (int o = 16; o > 0; o >>= 1)
            sm[hh] += __shfl_xor_sync(0xffffffffu, sm[hh], o);
    float rs[4] = {1.f / sm[0], 1.f / sm[1], 1.f / sm[2], 1.f / sm[3]};

    // phase 3: weighted aggregation, all lanes walk every edge (h rows coalesced)
    float acc[8] = {0, 0, 0, 0, 0, 0, 0, 0};
    for (int j = beg; j < end; j++) {
        int s = d_csr_src[j];
        float4 a4 = *(const float4*)&d_as[s * 4];
        float w0 = expf(lrelu(a4.x + adv[0]) - mx[0]) * rs[0];
        float w1 = expf(lrelu(a4.y + adv[1]) - mx[1]) * rs[1];
        float w2 = expf(lrelu(a4.z + adv[2]) - mx[2]) * rs[2];
        float w3 = expf(lrelu(a4.w + adv[3]) - mx[3]) * rs[3];
        const float* hr = &h[s * HC];
        acc[0] += w0 * hr[lane +   0]; acc[1] += w0 * hr[lane +  32];
        acc[2] += w1 * hr[lane +  64]; acc[3] += w1 * hr[lane +  96];
        acc[4] += w2 * hr[lane + 128]; acc[5] += w2 * hr[lane + 160];
        acc[6] += w3 * hr[lane + 192]; acc[7] += w3 * hr[lane + 224];
    }
#pragma unroll
    for (int i = 0; i < 8; i++) {
        int col = lane + 32 * i;
        float v = acc[i] + bias[col];
        out[n * HC + col] = v > 0.f ? v : 0.f;
    }
}

// ---------------- graph pooling (segment max over sorted batch) ----------------
__global__ void k_pool() {
    int g = blockIdx.x;
    int col = blockIdx.y * 128 + threadIdx.x;
    if (col >= GFD) return;
    const float* base; int stride, c;
    if (col < 64)       { base = d_n0; stride = 64;  c = col; }
    else if (col < 320) { base = d_x1; stride = 256; c = col - 64; }
    else if (col < 576) { base = d_x2; stride = 256; c = col - 320; }
    else                { base = d_x3; stride = 256; c = col - 576; }
    int s = d_gstart[g], e = d_gend[g];
    float v = -FLT_MAX;
    for (int i = s; i < e; i++) v = fmaxf(v, base[i * stride + c]);
    d_gfeat[g * GFD + col] = v;
}

// ---------------- head MLPs ----------------
__global__ void k_latent(const float* __restrict__ W, const float* __restrict__ b) {
    __shared__ float gs[GFD];
    int g = blockIdx.x, t = threadIdx.x;
    for (int i = t; i < GFD; i += 256) gs[i] = d_gfeat[g * GFD + i];
    __syncthreads();
    float acc = b[t];
    for (int k = 0; k < GFD; k++) acc += gs[k] * W[k * LATD + t];
    d_lat[g * LATD + t] = acc;
}

__global__ void k_heads(const float* __restrict__ muW, const float* __restrict__ mub,
                        const float* __restrict__ vW, const float* __restrict__ vb,
                        float* __restrict__ out) {
    __shared__ float ls[LATD];
    int g = blockIdx.x, t = threadIdx.x;
    ls[t] = d_lat[g * LATD + t];
    __syncthreads();
    float am = mub[t], av = vb[t];
    for (int k = 0; k < LATD; k++) {
        float lv = ls[k];
        am += lv * muW[k * LATD + t];
        av += lv * vW[k * LATD + t];
    }
    out[g * LATD + t] = am;
    out[GG * LATD + g * LATD + t] = av;
}

// ---------------- launch ----------------
extern "C" void kernel_launch(void* const* d_in, const int* in_sizes, int n_in,
                              void* d_out, int out_size) {
    const float* bf   = (const float*)d_in[0];
    const int*   ei   = (const int*)  d_in[1];
    const int*   batch= (const int*)  d_in[2];
    const float* bfW  = (const float*)d_in[3];
    const float* bfb  = (const float*)d_in[4];
    const float* W1   = (const float*)d_in[5];
    const float* as1  = (const float*)d_in[6];
    const float* ad1  = (const float*)d_in[7];
    const float* b1   = (const float*)d_in[8];
    const float* W2   = (const float*)d_in[9];
    const float* as2  = (const float*)d_in[10];
    const float* ad2  = (const float*)d_in[11];
    const float* b2   = (const float*)d_in[12];
    const float* W3   = (const float*)d_in[13];
    const float* as3  = (const float*)d_in[14];
    const float* ad3  = (const float*)d_in[15];
    const float* b3   = (const float*)d_in[16];
    const float* aggW = (const float*)d_in[17];
    const float* aggb = (const float*)d_in[18];
    const float* muW  = (const float*)d_in[19];
    const float* mub  = (const float*)d_in[20];
    const float* vW   = (const float*)d_in[21];
    const float* vb   = (const float*)d_in[22];
    float* out = (float*)d_out;

    float *p_n0, *p_h, *p_x1, *p_x2, *p_x3;
    cudaGetSymbolAddress((void**)&p_n0, d_n0);
    cudaGetSymbolAddress((void**)&p_h,  d_h);
    cudaGetSymbolAddress((void**)&p_x1, d_x1);
    cudaGetSymbolAddress((void**)&p_x2, d_x2);
    cudaGetSymbolAddress((void**)&p_x3, d_x3);

    const int T = 256;
    // CSR build
    k_init   <<<(NN + T - 1) / T, T>>>();
    k_deg    <<<(EL + T - 1) / T, T>>>(ei);
    k_scan1  <<<NB1, SCAN_B>>>();
    k_scan2  <<<1, 32>>>();
    k_scan3  <<<(NN + T - 1) / T, T>>>();
    k_cursor <<<(NN + T - 1) / T, T>>>();
    k_scatter<<<(EL + T - 1) / T, T>>>(ei);
    k_bounds <<<(NN + T - 1) / T, T>>>(batch);

    // input projection
    k_proj<<<(NN * FD + T - 1) / T, T>>>(bf, bfW, bfb);

    dim3 ggrid((NN + 63) / 64, 4);
    int wgrid = (NN + 7) / 8;   // 8 warps per 256-thread block

    // layer 1
    k_gemm<<<ggrid, 256>>>(p_n0, W1, p_h, FD);
    k_att <<<wgrid, 256>>>(p_h, as1, ad1);
    k_agg <<<wgrid, 256>>>(p_h, b1, p_x1);
    // layer 2
    k_gemm<<<ggrid, 256>>>(p_x1, W2, p_h, HC);
    k_att <<<wgrid, 256>>>(p_h, as2, ad2);
    k_agg <<<wgrid, 256>>>(p_h, b2, p_x2);
    // layer 3
    k_gemm<<<ggrid, 256>>>(p_x2, W3, p_h, HC);
    k_att <<<wgrid, 256>>>(p_h, as3, ad3);
    k_agg <<<wgrid, 256>>>(p_h, b3, p_x3);

    // pooling + heads
    dim3 pgrid(GG, (GFD + 127) / 128);
    k_pool  <<<pgrid, 128>>>();
    k_latent<<<GG, 256>>>(aggW, aggb);
    k_heads <<<GG, 256>>>(muW, mub, vW, vb, out);
}